// round 16
// baseline (speedup 1.0000x reference)
#include <cuda_runtime.h>
#include <math.h>
#include <stdint.h>

#define BB 2
#define LL 1024
#define DD 768
#define HH 12
#define DHH 64
#define DP 32
#define MLPD 3072
#define NLAYER 4
#define WIN 128
#define BW 264
#define EPS_RMS 1.1920929e-07f
#define EPS_LN 1e-5f

// ---------------- scratch ----------------
__device__ float g_qkv[BB * LL * 3 * DD];
__device__ float g_y[BB * LL * DD];
__device__ float g_u[BB * LL * MLPD];
__device__ float g_bias[NLAYER * BB * LL * BW];
__device__ float g_cos[LL * 32];
__device__ float g_sin[LL * 32];
__device__ float g_inv[BB * LL];
__device__ uint32_t g_qh[BB * HH * LL * 32], g_ql[BB * HH * LL * 32];
__device__ uint32_t g_kh[BB * HH * LL * 32], g_kl[BB * HH * LL * 32];
__device__ uint32_t g_vh[BB * HH * LL * 32], g_vl[BB * HH * LL * 32];

// ---------------- helpers ----------------
__device__ __forceinline__ float warp_sum(float v) {
#pragma unroll
    for (int o = 16; o; o >>= 1) v += __shfl_xor_sync(0xffffffffu, v, o);
    return v;
}
__device__ __forceinline__ float gelu_f(float x) {
    return 0.5f * x * (1.0f + erff(x * 0.70710678118654752f));
}
__device__ __forceinline__ uint32_t packbf(float lo, float hi) {
    uint32_t r;
    asm("cvt.rn.bf16x2.f32 %0, %1, %2;" : "=r"(r) : "f"(hi), "f"(lo));
    return r;
}
__device__ __forceinline__ void split2(float a, float b, uint32_t& hi, uint32_t& lo) {
    hi = packbf(a, b);
    lo = packbf(a - __uint_as_float(hi << 16), b - __uint_as_float(hi & 0xffff0000u));
}

#define MMA_BF16(d, a0, a1, a2, a3, b0, b1)                                          \
    asm volatile(                                                                    \
        "mma.sync.aligned.m16n8k16.row.col.f32.bf16.bf16.f32 "                       \
        "{%0,%1,%2,%3},{%4,%5,%6,%7},{%8,%9},{%0,%1,%2,%3};"                         \
        : "+f"(d[0]), "+f"(d[1]), "+f"(d[2]), "+f"(d[3])                             \
        : "r"(a0), "r"(a1), "r"(a2), "r"(a3), "r"(b0), "r"(b1))

#define LDSM4(r, addr)                                                               \
    asm volatile("ldmatrix.sync.aligned.m8n8.x4.shared.b16 {%0,%1,%2,%3},[%4];"      \
                 : "=r"(r[0]), "=r"(r[1]), "=r"(r[2]), "=r"(r[3]) : "r"(addr))

#define LDSM4T(r, addr)                                                              \
    asm volatile("ldmatrix.sync.aligned.m8n8.x4.trans.shared.b16 {%0,%1,%2,%3},[%4];"\
                 : "=r"(r[0]), "=r"(r[1]), "=r"(r[2]), "=r"(r[3]) : "r"(addr))

// ---------------- rope table (fp64 once) ----------------
__global__ void rope_table_kernel() {
    int idx = blockIdx.x * blockDim.x + threadIdx.x;
    if (idx >= LL * 32) return;
    int i = idx & 31;
    int pos = idx >> 5;
    double invf = exp(-((double)(2 * i) / 64.0) * 9.210340371976184);
    double ang = (double)pos * invf;
    g_cos[idx] = (float)cos(ang);
    g_sin[idx] = (float)sin(ang);
}

// ---------------- pair-bias (all layers, windowed) ----------------
__global__ void bias_kernel(const float* __restrict__ pair,
                            const float* __restrict__ ln_g, const float* __restrict__ ln_b,
                            const float* __restrict__ pb_w, const float* __restrict__ pb_b,
                            float* __restrict__ bout) {
    const int WN = 2 * WIN + 1;
    int gw = (blockIdx.x * blockDim.x + threadIdx.x) >> 5;
    int lane = threadIdx.x & 31;
    int total = BB * LL * WN;
    if (gw >= total) return;
    int w = gw % WN;
    int t = gw / WN;
    int qq = t % LL;
    int b = t / LL;
    int j = qq - WIN + w;
    if (j < 0 || j >= LL) return;

    float x = pair[(((size_t)b * LL + qq) * LL + j) * DP + lane];
    float m = warp_sum(x) * (1.0f / 32.0f);
    float d = x - m;
    float var = warp_sum(d * d) * (1.0f / 32.0f);
    float nm = d * rsqrtf(var + EPS_LN);
#pragma unroll
    for (int l = 0; l < NLAYER; l++) {
        float wv = pb_w[l * DP + lane];
        float contrib = (nm * ln_g[l * DP + lane] + ln_b[l * DP + lane]) * wv;
        float sum = warp_sum(contrib);
        if (lane == 0)
            bout[(((size_t)l * BB + b) * LL + qq) * BW + w] = sum + pb_b[l];
    }
}

// ---------------- per-row inv rms (one warp per row) ----------------
__global__ void invrms_kernel(const float* __restrict__ s, float* __restrict__ invv) {
    int row = blockIdx.x * 8 + (threadIdx.x >> 5);
    int lane = threadIdx.x & 31;
    const float* x = s + (size_t)row * DD;
    float ss = 0.f;
#pragma unroll
    for (int i = 0; i < 24; i++) {
        float v = x[lane + 32 * i];
        ss = fmaf(v, v, ss);
    }
    ss = warp_sum(ss);
    if (lane == 0) invv[row] = rsqrtf(ss * (1.0f / (float)DD) + EPS_RMS);
}

// ---------------- tensor-core GEMM (3xBF16) — R6 data path, parametric warp count ----------------
// out[rows,N] = (invr? A*invr : A)[rows,K] @ W[M,K]^T + bias. BN=128, BK=32.
// NTH=256: 8 warps; NTH=512: 16 warps (warp tile 32x32, 4x4 grid).
template <int BM, int NTH, int ACT, int RESID, int NORM>
__global__ void __launch_bounds__(NTH) gemm_tc(
    const float* __restrict__ A, const float* __restrict__ W,
    const float* __restrict__ bias, float* __restrict__ out,
    const float* __restrict__ invr, int K, int N) {
    constexpr int NWARPS = NTH / 32;
    constexpr int NWM = BM / 32;
    constexpr int NWN = NWARPS / NWM;
    constexpr int WCOLS = 128 / NWN;
    constexpr int NT = WCOLS / 8;
    constexpr int NP = NT / 2;
    constexpr int RST = NTH / 8;          // load row stride
    constexpr int ACH = BM / RST;
    constexpr int WCH = 128 / RST;

    __shared__ uint32_t SA[2][BM][20];
    __shared__ uint32_t SW[2][128][20];

    const int tid = threadIdx.x;
    const int lane = tid & 31;
    const int w = tid >> 5;
    const int wm = w / NWN;
    const int wn = w % NWN;
    const int g = lane >> 2;
    const int tg = lane & 3;
    const int row0 = blockIdx.y * BM;
    const int col0 = blockIdx.x * 128;

    const int lr = tid >> 3;              // 0..RST-1
    const int kq = (tid & 7) * 4;

    const float* Ap[ACH];
    float scl[ACH];
#pragma unroll
    for (int c = 0; c < ACH; c++) {
        Ap[c] = A + (size_t)(row0 + lr + RST * c) * K + kq;
        scl[c] = NORM ? invr[row0 + lr + RST * c] : 1.0f;
    }
    const float* Wp[WCH];
#pragma unroll
    for (int c = 0; c < WCH; c++)
        Wp[c] = W + (size_t)(col0 + lr + RST * c) * K + kq;

    uint32_t saBase = (uint32_t)__cvta_generic_to_shared(&SA[0][0][0]);
    uint32_t swBase = (uint32_t)__cvta_generic_to_shared(&SW[0][0][0]);
    const uint32_t aAddr = saBase + (((wm * 32 + (lane & 15)) * 20) + (lane >> 4) * 4) * 4;
    const uint32_t bAddr = swBase +
        (((wn * WCOLS + (lane & 7) + ((lane >> 4) << 3)) * 20) + ((lane >> 3) & 1) * 4) * 4;
    constexpr uint32_t AHL = BM * 20 * 4;
    constexpr uint32_t WHL = 128 * 20 * 4;

    float acc[2][NT][4];
#pragma unroll
    for (int a = 0; a < 2; a++)
#pragma unroll
        for (int b = 0; b < NT; b++)
#pragma unroll
            for (int c = 0; c < 4; c++) acc[a][b][c] = 0.f;

    const int nk = K / 32;
    float4 pa[ACH], pw[WCH];
#pragma unroll
    for (int c = 0; c < ACH; c++) pa[c] = *(const float4*)(Ap[c]);
#pragma unroll
    for (int c = 0; c < WCH; c++) pw[c] = *(const float4*)(Wp[c]);

    for (int i = 0; i < nk; i++) {
#pragma unroll
        for (int c = 0; c < ACH; c++) {
            int m = lr + RST * c;
            float x0 = pa[c].x, x1 = pa[c].y, x2 = pa[c].z, x3 = pa[c].w;
            if (NORM) { x0 *= scl[c]; x1 *= scl[c]; x2 *= scl[c]; x3 *= scl[c]; }
            uint32_t h0, l0h, h1, l1h;
            split2(x0, x1, h0, l0h);
            split2(x2, x3, h1, l1h);
            SA[0][m][(kq >> 1)] = h0;
            SA[0][m][(kq >> 1) + 1] = h1;
            SA[1][m][(kq >> 1)] = l0h;
            SA[1][m][(kq >> 1) + 1] = l1h;
        }
#pragma unroll
        for (int c = 0; c < WCH; c++) {
            int n = lr + RST * c;
            uint32_t h0, l0h, h1, l1h;
            split2(pw[c].x, pw[c].y, h0, l0h);
            split2(pw[c].z, pw[c].w, h1, l1h);
            SW[0][n][(kq >> 1)] = h0;
            SW[0][n][(kq >> 1) + 1] = h1;
            SW[1][n][(kq >> 1)] = l0h;
            SW[1][n][(kq >> 1) + 1] = l1h;
        }
        __syncthreads();
        if (i + 1 < nk) {
            int ko = (i + 1) * 32;
#pragma unroll
            for (int c = 0; c < ACH; c++) pa[c] = *(const float4*)(Ap[c] + ko);
#pragma unroll
            for (int c = 0; c < WCH; c++) pw[c] = *(const float4*)(Wp[c] + ko);
        }
#pragma unroll
        for (int kk = 0; kk < 2; kk++) {
            uint32_t ah[2][4], al[2][4];
#pragma unroll
            for (int mt = 0; mt < 2; mt++) {
                uint32_t base = aAddr + mt * 1280 + kk * 32;
                LDSM4(ah[mt], base);
                LDSM4(al[mt], base + AHL);
            }
#pragma unroll
            for (int p = 0; p < NP; p++) {
                uint32_t bh[4], bl[4];
                uint32_t base = bAddr + p * 1280 + kk * 32;
                LDSM4(bh, base);
                LDSM4(bl, base + WHL);
#pragma unroll
                for (int mt = 0; mt < 2; mt++) {
                    MMA_BF16(acc[mt][2 * p], ah[mt][0], ah[mt][1], ah[mt][2], ah[mt][3], bh[0], bh[1]);
                    MMA_BF16(acc[mt][2 * p], al[mt][0], al[mt][1], al[mt][2], al[mt][3], bh[0], bh[1]);
                    MMA_BF16(acc[mt][2 * p], ah[mt][0], ah[mt][1], ah[mt][2], ah[mt][3], bl[0], bl[1]);
                    MMA_BF16(acc[mt][2 * p + 1], ah[mt][0], ah[mt][1], ah[mt][2], ah[mt][3], bh[2], bh[3]);
                    MMA_BF16(acc[mt][2 * p + 1], al[mt][0], al[mt][1], al[mt][2], al[mt][3], bh[2], bh[3]);
                    MMA_BF16(acc[mt][2 * p + 1], ah[mt][0], ah[mt][1], ah[mt][2], ah[mt][3], bl[2], bl[3]);
                }
            }
        }
        __syncthreads();
    }

#pragma unroll
    for (int mt = 0; mt < 2; mt++) {
#pragma unroll
        for (int nt = 0; nt < NT; nt++) {
            int col = col0 + wn * WCOLS + nt * 8 + tg * 2;
            float b0 = bias[col], b1 = bias[col + 1];
#pragma unroll
            for (int half = 0; half < 2; half++) {
                int row = row0 + wm * 32 + mt * 16 + g + half * 8;
                float v0 = acc[mt][nt][half * 2] + b0;
                float v1 = acc[mt][nt][half * 2 + 1] + b1;
                if (ACT == 1) { v0 = gelu_f(v0); v1 = gelu_f(v1); }
                float* op = out + (size_t)row * N + col;
                if (RESID) { v0 += op[0]; v1 += op[1]; }
                op[0] = v0; op[1] = v1;
            }
        }
    }
}

// ---------------- RoPE + pre-split bf16 hi/lo q/k/v: [B,H,L,32] u32 ----------------
__global__ void rope_kernel(const float* __restrict__ qkv,
                            uint32_t* __restrict__ qh, uint32_t* __restrict__ ql,
                            uint32_t* __restrict__ kh, uint32_t* __restrict__ kl,
                            uint32_t* __restrict__ vh, uint32_t* __restrict__ vl) {
    int idx = blockIdx.x * blockDim.x + threadIdx.x;
    if (idx >= BB * LL * DD / 2) return;
    int wd = idx & 31;
    int h = (idx >> 5) % HH;
    int pos = (idx / (DD / 2)) % LL;
    int b = idx / (LL * (DD / 2));
    int d = wd * 2;

    const float* base = qkv + ((size_t)b * LL + pos) * 3 * DD;
    float q0 = base[h * DHH + d], q1 = base[h * DHH + d + 1];
    float k0 = base[DD + h * DHH + d], k1 = base[DD + h * DHH + d + 1];
    float v0 = base[2 * DD + h * DHH + d], v1 = base[2 * DD + h * DHH + d + 1];
    float c0 = g_cos[pos * 32 + (d & 31)], s0 = g_sin[pos * 32 + (d & 31)];
    float c1 = g_cos[pos * 32 + ((d + 1) & 31)], s1 = g_sin[pos * 32 + ((d + 1) & 31)];
    float qr0, qr1, kr0, kr1;
    if (d < 32) {
        qr0 = q0 * c0 - base[h * DHH + d + 32] * s0;
        qr1 = q1 * c1 - base[h * DHH + d + 33] * s1;
        kr0 = k0 * c0 - base[DD + h * DHH + d + 32] * s0;
        kr1 = k1 * c1 - base[DD + h * DHH + d + 33] * s1;
    } else {
        qr0 = q0 * c0 + base[h * DHH + d - 32] * s0;
        qr1 = q1 * c1 + base[h * DHH + d - 31] * s1;
        kr0 = k0 * c0 + base[DD + h * DHH + d - 32] * s0;
        kr1 = k1 * c1 + base[DD + h * DHH + d - 31] * s1;
    }
    size_t o = (((size_t)b * HH + h) * LL + pos) * 32 + wd;
    uint32_t hi, lo;
    split2(qr0, qr1, hi, lo); qh[o] = hi; ql[o] = lo;
    split2(kr0, kr1, hi, lo); kh[o] = hi; kl[o] = lo;
    split2(v0, v1, hi, lo);   vh[o] = hi; vl[o] = lo;
}

// ---------------- tensor-core windowed flash attention (3xBF16, pre-split inputs) ----------------
__global__ void __launch_bounds__(256) attn_tc(
    const uint32_t* __restrict__ qh, const uint32_t* __restrict__ ql,
    const uint32_t* __restrict__ kh, const uint32_t* __restrict__ kl,
    const uint32_t* __restrict__ vh, const uint32_t* __restrict__ vl,
    const float* __restrict__ biasb, float* __restrict__ y) {
    __shared__ uint32_t SK[2 * 64 * 36];
    __shared__ uint32_t SV[2 * 64 * 36];

    const int q0 = blockIdx.x * 64;
    const int hh = blockIdx.y, b = blockIdx.z;
    const int tid = threadIdx.x, lane = tid & 31, w = tid >> 5;
    const int wg = w >> 2, mt = w & 3;
    const int g = lane >> 2, tg = lane & 3;
    const int m0 = mt * 16;

    const int jstart = max(q0 - WIN, 0);
    const int jend = min(q0 + 64 + WIN, LL);
    const int nt = (jend - jstart) >> 6;

    const size_t bho = ((size_t)b * HH + hh) * LL * 32;
    const float* bb = biasb + (size_t)b * LL * BW;

    {
        int row = tid >> 2, seg = tid & 3;
        size_t off = bho + (size_t)(q0 + row) * 32 + seg * 8;
        uint32_t* dh_ = SK + row * 36 + seg * 8;
        uint32_t* dl_ = SK + 2304 + row * 36 + seg * 8;
        *(uint4*)(dh_) = *(const uint4*)(qh + off);
        *(uint4*)(dh_ + 4) = *(const uint4*)(qh + off + 4);
        *(uint4*)(dl_) = *(const uint4*)(ql + off);
        *(uint4*)(dl_ + 4) = *(const uint4*)(ql + off + 4);
    }
    __syncthreads();
    uint32_t qfh[4][4], qfl[4][4];
    {
        uint32_t qA = (uint32_t)__cvta_generic_to_shared(SK) +
                      (((m0 + (lane & 15)) * 36 + (lane >> 4) * 4) << 2);
#pragma unroll
        for (int kk = 0; kk < 4; kk++) {
            LDSM4(qfh[kk], qA + kk * 32);
            LDSM4(qfl[kk], qA + 9216 + kk * 32);
        }
    }
    __syncthreads();

    const uint32_t kA = (uint32_t)__cvta_generic_to_shared(SK) +
        ((((lane & 7) + ((lane >> 4) << 3) + wg * 32) * 36 + ((lane >> 3) & 1) * 4) << 2);
    const uint32_t vA = (uint32_t)__cvta_generic_to_shared(SV) +
        ((((lane & 15) + wg * 32) * 36 + (lane >> 4) * 4) << 2);

    float mX0 = -3.0e38f, mX1 = -3.0e38f, lX0 = 0.f, lX1 = 0.f;
    float o[8][4];
#pragma unroll
    for (int d = 0; d < 8; d++)
#pragma unroll
        for (int c = 0; c < 4; c++) o[d][c] = 0.f;

    const int qi0 = q0 + m0 + g;
    const float* brow0 = bb + (size_t)qi0 * BW;
    const float* brow1 = bb + (size_t)(qi0 + 8) * BW;

    for (int t = 0; t < nt; t++) {
        int j0 = jstart + t * 64;
        {
            int row = tid >> 2, seg = tid & 3;
            size_t off = bho + (size_t)(j0 + row) * 32 + seg * 8;
            uint32_t* kh_ = SK + row * 36 + seg * 8;
            uint32_t* kl_ = SK + 2304 + row * 36 + seg * 8;
            uint32_t* vh_ = SV + row * 36 + seg * 8;
            uint32_t* vl_ = SV + 2304 + row * 36 + seg * 8;
            *(uint4*)(kh_) = *(const uint4*)(kh + off);
            *(uint4*)(kh_ + 4) = *(const uint4*)(kh + off + 4);
            *(uint4*)(kl_) = *(const uint4*)(kl + off);
            *(uint4*)(kl_ + 4) = *(const uint4*)(kl + off + 4);
            *(uint4*)(vh_) = *(const uint4*)(vh + off);
            *(uint4*)(vh_ + 4) = *(const uint4*)(vh + off + 4);
            *(uint4*)(vl_) = *(const uint4*)(vl + off);
            *(uint4*)(vl_ + 4) = *(const uint4*)(vl + off + 4);
        }
        __syncthreads();

        float acc[4][4];
#pragma unroll
        for (int d = 0; d < 4; d++)
#pragma unroll
            for (int c = 0; c < 4; c++) acc[d][c] = 0.f;
#pragma unroll
        for (int kk = 0; kk < 4; kk++) {
#pragma unroll
            for (int pr = 0; pr < 2; pr++) {
                uint32_t bh4[4], bl4[4];
                uint32_t a = kA + pr * 2304 + kk * 32;
                LDSM4(bh4, a);
                LDSM4(bl4, a + 9216);
                MMA_BF16(acc[2 * pr], qfh[kk][0], qfh[kk][1], qfh[kk][2], qfh[kk][3], bh4[0], bh4[1]);
                MMA_BF16(acc[2 * pr], qfl[kk][0], qfl[kk][1], qfl[kk][2], qfl[kk][3], bh4[0], bh4[1]);
                MMA_BF16(acc[2 * pr], qfh[kk][0], qfh[kk][1], qfh[kk][2], qfh[kk][3], bl4[0], bl4[1]);
                MMA_BF16(acc[2 * pr + 1], qfh[kk][0], qfh[kk][1], qfh[kk][2], qfh[kk][3], bh4[2], bh4[3]);
                MMA_BF16(acc[2 * pr + 1], qfl[kk][0], qfl[kk][1], qfl[kk][2], qfl[kk][3], bh4[2], bh4[3]);
                MMA_BF16(acc[2 * pr + 1], qfh[kk][0], qfh[kk][1], qfh[kk][2], qfh[kk][3], bl4[2], bl4[3]);
            }
        }

        bool needmask = (j0 < q0 - 65) || (j0 > q0 + 65);
        int jb = j0 + wg * 32 + 2 * tg;
#pragma unroll
        for (int d = 0; d < 4; d++) {
            int j = jb + 8 * d;
            int i0 = j - qi0 + WIN;
            float b00 = brow0[min(max(i0, 0), 256)];
            float b01 = brow0[min(max(i0 + 1, 0), 256)];
            float b10 = brow1[min(max(i0 - 8, 0), 256)];
            float b11 = brow1[min(max(i0 - 7, 0), 256)];
            float s0 = fmaf(acc[d][0], 0.125f, b00);
            float s1 = fmaf(acc[d][1], 0.125f, b01);
            float s2 = fmaf(acc[d][2], 0.125f, b10);
            float s3 = fmaf(acc[d][3], 0.125f, b11);
            if (needmask) {
                if ((unsigned)i0 > 256u) s0 = -3.0e38f;
                if ((unsigned)(i0 + 1) > 256u) s1 = -3.0e38f;
                if ((unsigned)(i0 - 8) > 256u) s2 = -3.0e38f;
                if ((unsigned)(i0 - 7) > 256u) s3 = -3.0e38f;
            }
            acc[d][0] = s0; acc[d][1] = s1; acc[d][2] = s2; acc[d][3] = s3;
        }
        float tm0 = -3.0e38f, tm1 = -3.0e38f;
#pragma unroll
        for (int d = 0; d < 4; d++) {
            tm0 = fmaxf(tm0, fmaxf(acc[d][0], acc[d][1]));
            tm1 = fmaxf(tm1, fmaxf(acc[d][2], acc[d][3]));
        }
        tm0 = fmaxf(tm0, __shfl_xor_sync(0xffffffffu, tm0, 1));
        tm0 = fmaxf(tm0, __shfl_xor_sync(0xffffffffu, tm0, 2));
        tm1 = fmaxf(tm1, __shfl_xor_sync(0xffffffffu, tm1, 1));
        tm1 = fmaxf(tm1, __shfl_xor_sync(0xffffffffu, tm1, 2));
        float mn0 = fmaxf(mX0, tm0), mn1 = fmaxf(mX1, tm1);
        float f0 = __expf(mX0 - mn0), f1 = __expf(mX1 - mn1);
        mX0 = mn0; mX1 = mn1;
        lX0 *= f0; lX1 *= f1;
#pragma unroll
        for (int d = 0; d < 8; d++) {
            o[d][0] *= f0; o[d][1] *= f0; o[d][2] *= f1; o[d][3] *= f1;
        }
#pragma unroll
        for (int d = 0; d < 4; d++) {
            float p0 = __expf(acc[d][0] - mn0);
            float p1 = __expf(acc[d][1] - mn0);
            float p2 = __expf(acc[d][2] - mn1);
            float p3 = __expf(acc[d][3] - mn1);
            lX0 += p0 + p1; lX1 += p2 + p3;
            acc[d][0] = p0; acc[d][1] = p1; acc[d][2] = p2; acc[d][3] = p3;
        }
#pragma unroll
        for (int c = 0; c < 2; c++) {
            int d0 = 2 * c, d1 = 2 * c + 1;
            uint32_t ph0, pl0, ph1, pl1, ph2, pl2, ph3, pl3;
            split2(acc[d0][0], acc[d0][1], ph0, pl0);
            split2(acc[d0][2], acc[d0][3], ph1, pl1);
            split2(acc[d1][0], acc[d1][1], ph2, pl2);
            split2(acc[d1][2], acc[d1][3], ph3, pl3);
#pragma unroll
            for (int pr = 0; pr < 4; pr++) {
                uint32_t vh4[4], vl4[4];
                uint32_t a = vA + c * 2304 + pr * 32;
                LDSM4T(vh4, a);
                LDSM4T(vl4, a + 9216);
                MMA_BF16(o[2 * pr], ph0, ph1, ph2, ph3, vh4[0], vh4[1]);
                MMA_BF16(o[2 * pr], pl0, pl1, pl2, pl3, vh4[0], vh4[1]);
                MMA_BF16(o[2 * pr], ph0, ph1, ph2, ph3, vl4[0], vl4[1]);
                MMA_BF16(o[2 * pr + 1], ph0, ph1, ph2, ph3, vh4[2], vh4[3]);
                MMA_BF16(o[2 * pr + 1], pl0, pl1, pl2, pl3, vh4[2], vh4[3]);
                MMA_BF16(o[2 * pr + 1], ph0, ph1, ph2, ph3, vl4[2], vl4[3]);
            }
        }
        __syncthreads();
    }

    lX0 += __shfl_xor_sync(0xffffffffu, lX0, 1);
    lX0 += __shfl_xor_sync(0xffffffffu, lX0, 2);
    lX1 += __shfl_xor_sync(0xffffffffu, lX1, 1);
    lX1 += __shfl_xor_sync(0xffffffffu, lX1, 2);

    float* mo = (float*)SK;
    float* ml = (float*)SV;
    if (wg == 1) {
#pragma unroll
        for (int d = 0; d < 8; d++) {
            *(float2*)&mo[(m0 + g) * 66 + 8 * d + 2 * tg] = make_float2(o[d][0], o[d][1]);
            *(float2*)&mo[(m0 + 8 + g) * 66 + 8 * d + 2 * tg] = make_float2(o[d][2], o[d][3]);
        }
        if (tg == 0) {
            ml[(m0 + g) * 2] = mX0; ml[(m0 + g) * 2 + 1] = lX0;
            ml[(m0 + 8 + g) * 2] = mX1; ml[(m0 + 8 + g) * 2 + 1] = lX1;
        }
    }
    __syncthreads();
    if (wg == 0) {
        int r0 = m0 + g, r1 = m0 + 8 + g;
        float om0 = ml[r0 * 2], ol0 = ml[r0 * 2 + 1];
        float om1 = ml[r1 * 2], ol1 = ml[r1 * 2 + 1];
        float mnA = fmaxf(mX0, om0);
        float fa = __expf(mX0 - mnA), fb = __expf(om0 - mnA);
        float invA = 1.0f / (lX0 * fa + ol0 * fb);
        float mnB = fmaxf(mX1, om1);
        float fc = __expf(mX1 - mnB), fd = __expf(om1 - mnB);
        float invB = 1.0f / (lX1 * fc + ol1 * fd);
        float* y0 = y + ((size_t)(b * LL + q0 + r0)) * DD + hh * DHH;
        float* y1 = y + ((size_t)(b * LL + q0 + r1)) * DD + hh * DHH;
#pragma unroll
        for (int d = 0; d < 8; d++) {
            float2 e0 = *(float2*)&mo[r0 * 66 + 8 * d + 2 * tg];
            float2 e1 = *(float2*)&mo[r1 * 66 + 8 * d + 2 * tg];
            float2 w0, w1;
            w0.x = (o[d][0] * fa + e0.x * fb) * invA;
            w0.y = (o[d][1] * fa + e0.y * fb) * invA;
            w1.x = (o[d][2] * fc + e1.x * fd) * invB;
            w1.y = (o[d][3] * fc + e1.y * fd) * invB;
            *(float2*)&y0[8 * d + 2 * tg] = w0;
            *(float2*)&y1[8 * d + 2 * tg] = w1;
        }
    }
}

// ---------------- driver ----------------
extern "C" void kernel_launch(void* const* d_in, const int* in_sizes, int n_in,
                              void* d_out, int out_size) {
    const float* s_in  = (const float*)d_in[0];
    const float* pair  = (const float*)d_in[1];
    const float* qkv_w = (const float*)d_in[2];
    const float* qkv_b = (const float*)d_in[3];
    const float* out_w = (const float*)d_in[4];
    const float* out_b = (const float*)d_in[5];
    const float* fc1_w = (const float*)d_in[6];
    const float* fc1_b = (const float*)d_in[7];
    const float* fc2_w = (const float*)d_in[8];
    const float* fc2_b = (const float*)d_in[9];
    const float* ln_g  = (const float*)d_in[10];
    const float* ln_b  = (const float*)d_in[11];
    const float* pb_w  = (const float*)d_in[12];
    const float* pb_b  = (const float*)d_in[13];
    float* s = (float*)d_out;

    float *p_qkv, *p_y, *p_u, *p_bias, *p_inv;
    uint32_t *p_qh, *p_ql, *p_kh, *p_kl, *p_vh, *p_vl;
    cudaGetSymbolAddress((void**)&p_qkv, g_qkv);
    cudaGetSymbolAddress((void**)&p_y, g_y);
    cudaGetSymbolAddress((void**)&p_u, g_u);
    cudaGetSymbolAddress((void**)&p_bias, g_bias);
    cudaGetSymbolAddress((void**)&p_inv, g_inv);
    cudaGetSymbolAddress((void**)&p_qh, g_qh);
    cudaGetSymbolAddress((void**)&p_ql, g_ql);
    cudaGetSymbolAddress((void**)&p_kh, g_kh);
    cudaGetSymbolAddress((void**)&p_kl, g_kl);
    cudaGetSymbolAddress((void**)&p_vh, g_vh);
    cudaGetSymbolAddress((void**)&p_vl, g_vl);

    cudaMemcpyAsync(s, s_in, sizeof(float) * BB * LL * DD, cudaMemcpyDeviceToDevice, 0);

    rope_table_kernel<<<(LL * 32 + 255) / 256, 256>>>();

    {
        int nwarps = BB * LL * 257;
        int blocks = (nwarps * 32 + 255) / 256;
        bias_kernel<<<blocks, 256>>>(pair, ln_g, ln_b, pb_w, pb_b, p_bias);
    }

    const int NROWS = BB * LL;
    for (int l = 0; l < NLAYER; l++) {
        invrms_kernel<<<NROWS / 8, 256>>>(s, p_inv);
        gemm_tc<128, 512, 0, 0, 1><<<dim3(3 * DD / 128, NROWS / 128), 512>>>(
            s, qkv_w + (size_t)l * 3 * DD * DD, qkv_b + (size_t)l * 3 * DD, p_qkv, p_inv, DD, 3 * DD);
        rope_kernel<<<(BB * LL * DD / 2 + 255) / 256, 256>>>(
            p_qkv, p_qh, p_ql, p_kh, p_kl, p_vh, p_vl);
        attn_tc<<<dim3(LL / 64, HH, BB), 256>>>(
            p_qh, p_ql, p_kh, p_kl, p_vh, p_vl, p_bias + (size_t)l * BB * LL * BW, p_y);
        gemm_tc<64, 256, 0, 1, 0><<<dim3(DD / 128, NROWS / 64), 256>>>(
            p_y, out_w + (size_t)l * DD * DD, out_b + (size_t)l * DD, s, nullptr, DD, DD);
        invrms_kernel<<<NROWS / 8, 256>>>(s, p_inv);
        gemm_tc<128, 512, 1, 0, 1><<<dim3(MLPD / 128, NROWS / 128), 512>>>(
            s, fc1_w + (size_t)l * MLPD * DD, fc1_b + (size_t)l * MLPD, p_u, p_inv, DD, MLPD);
        gemm_tc<64, 256, 0, 1, 0><<<dim3(DD / 128, NROWS / 64), 256>>>(
            p_u, fc2_w + (size_t)l * DD * MLPD, fc2_b + (size_t)l * DD, s, nullptr, MLPD, DD);
    }
}

// round 17
// speedup vs baseline: 1.0487x; 1.0487x over previous
#include <cuda_runtime.h>
#include <math.h>
#include <stdint.h>

#define BB 2
#define LL 1024
#define DD 768
#define HH 12
#define DHH 64
#define DP 32
#define MLPD 3072
#define NLAYER 4
#define WIN 128
#define BW 264
#define EPS_RMS 1.1920929e-07f
#define EPS_LN 1e-5f

// ---------------- scratch ----------------
__device__ float g_y[BB * LL * DD];
__device__ float g_u[BB * LL * MLPD];
__device__ float g_bias[NLAYER * BB * LL * BW];
__device__ float g_cos[LL * 32];
__device__ float g_sin[LL * 32];
__device__ float g_inv[BB * LL];
__device__ uint32_t g_qh[BB * HH * LL * 32], g_ql[BB * HH * LL * 32];
__device__ uint32_t g_kh[BB * HH * LL * 32], g_kl[BB * HH * LL * 32];
__device__ uint32_t g_vh[BB * HH * LL * 32], g_vl[BB * HH * LL * 32];

// ---------------- helpers ----------------
__device__ __forceinline__ float warp_sum(float v) {
#pragma unroll
    for (int o = 16; o; o >>= 1) v += __shfl_xor_sync(0xffffffffu, v, o);
    return v;
}
__device__ __forceinline__ float gelu_f(float x) {
    return 0.5f * x * (1.0f + erff(x * 0.70710678118654752f));
}
__device__ __forceinline__ uint32_t packbf(float lo, float hi) {
    uint32_t r;
    asm("cvt.rn.bf16x2.f32 %0, %1, %2;" : "=r"(r) : "f"(hi), "f"(lo));
    return r;
}
__device__ __forceinline__ void split2(float a, float b, uint32_t& hi, uint32_t& lo) {
    hi = packbf(a, b);
    lo = packbf(a - __uint_as_float(hi << 16), b - __uint_as_float(hi & 0xffff0000u));
}

#define MMA_BF16(d, a0, a1, a2, a3, b0, b1)                                          \
    asm volatile(                                                                    \
        "mma.sync.aligned.m16n8k16.row.col.f32.bf16.bf16.f32 "                       \
        "{%0,%1,%2,%3},{%4,%5,%6,%7},{%8,%9},{%0,%1,%2,%3};"                         \
        : "+f"(d[0]), "+f"(d[1]), "+f"(d[2]), "+f"(d[3])                             \
        : "r"(a0), "r"(a1), "r"(a2), "r"(a3), "r"(b0), "r"(b1))

#define LDSM4(r, addr)                                                               \
    asm volatile("ldmatrix.sync.aligned.m8n8.x4.shared.b16 {%0,%1,%2,%3},[%4];"      \
                 : "=r"(r[0]), "=r"(r[1]), "=r"(r[2]), "=r"(r[3]) : "r"(addr))

#define LDSM4T(r, addr)                                                              \
    asm volatile("ldmatrix.sync.aligned.m8n8.x4.trans.shared.b16 {%0,%1,%2,%3},[%4];"\
                 : "=r"(r[0]), "=r"(r[1]), "=r"(r[2]), "=r"(r[3]) : "r"(addr))

// ---------------- rope table (fp64 once) ----------------
__global__ void rope_table_kernel() {
    int idx = blockIdx.x * blockDim.x + threadIdx.x;
    if (idx >= LL * 32) return;
    int i = idx & 31;
    int pos = idx >> 5;
    double invf = exp(-((double)(2 * i) / 64.0) * 9.210340371976184);
    double ang = (double)pos * invf;
    g_cos[idx] = (float)cos(ang);
    g_sin[idx] = (float)sin(ang);
}

// ---------------- pair-bias (all layers, windowed) ----------------
__global__ void bias_kernel(const float* __restrict__ pair,
                            const float* __restrict__ ln_g, const float* __restrict__ ln_b,
                            const float* __restrict__ pb_w, const float* __restrict__ pb_b,
                            float* __restrict__ bout) {
    const int WN = 2 * WIN + 1;
    int gw = (blockIdx.x * blockDim.x + threadIdx.x) >> 5;
    int lane = threadIdx.x & 31;
    int total = BB * LL * WN;
    if (gw >= total) return;
    int w = gw % WN;
    int t = gw / WN;
    int qq = t % LL;
    int b = t / LL;
    int j = qq - WIN + w;
    if (j < 0 || j >= LL) return;

    float x = pair[(((size_t)b * LL + qq) * LL + j) * DP + lane];
    float m = warp_sum(x) * (1.0f / 32.0f);
    float d = x - m;
    float var = warp_sum(d * d) * (1.0f / 32.0f);
    float nm = d * rsqrtf(var + EPS_LN);
#pragma unroll
    for (int l = 0; l < NLAYER; l++) {
        float wv = pb_w[l * DP + lane];
        float contrib = (nm * ln_g[l * DP + lane] + ln_b[l * DP + lane]) * wv;
        float sum = warp_sum(contrib);
        if (lane == 0)
            bout[(((size_t)l * BB + b) * LL + qq) * BW + w] = sum + pb_b[l];
    }
}

// ---------------- per-row inv rms (one warp per row) ----------------
__global__ void invrms_kernel(const float* __restrict__ s, float* __restrict__ invv) {
    int row = blockIdx.x * 8 + (threadIdx.x >> 5);
    int lane = threadIdx.x & 31;
    const float* x = s + (size_t)row * DD;
    float ss = 0.f;
#pragma unroll
    for (int i = 0; i < 24; i++) {
        float v = x[lane + 32 * i];
        ss = fmaf(v, v, ss);
    }
    ss = warp_sum(ss);
    if (lane == 0) invv[row] = rsqrtf(ss * (1.0f / (float)DD) + EPS_RMS);
}

// ---------------- tensor-core GEMM (3xBF16) — R15 core + optional RoPE epilogue ----------------
// out[rows,N] = (invr? A*invr : A)[rows,K] @ W[M,K]^T + bias. BN=128, 256 thr, BK=32.
// ROPE=1 (requires BM=128): apply rotate-half RoPE + split bf16 hi/lo, write q/k/v arrays.
template <int BM, int ACT, int RESID, int NORM, int ROPE>
__global__ void __launch_bounds__(256) gemm_tc(
    const float* __restrict__ A, const float* __restrict__ W,
    const float* __restrict__ bias, float* __restrict__ out,
    const float* __restrict__ invr,
    uint32_t* __restrict__ oqh, uint32_t* __restrict__ oql,
    uint32_t* __restrict__ okh, uint32_t* __restrict__ okl,
    uint32_t* __restrict__ ovh, uint32_t* __restrict__ ovl,
    int K, int N) {
    constexpr int NWM = BM / 32;
    constexpr int NWN = 8 / NWM;
    constexpr int WCOLS = 128 / NWN;
    constexpr int NT = WCOLS / 8;
    constexpr int NP = NT / 2;
    constexpr int ACH = BM / 32;

    __shared__ uint32_t SA[2][BM][20];
    __shared__ uint32_t SW[2][128][20];

    const int tid = threadIdx.x;
    const int lane = tid & 31;
    const int w = tid >> 5;
    const int wm = w / NWN;
    const int wn = w % NWN;
    const int g = lane >> 2;
    const int tg = lane & 3;
    const int row0 = blockIdx.y * BM;
    const int col0 = blockIdx.x * 128;

    const int lr = tid >> 3;
    const int kq = (tid & 7) * 4;

    const float* Ap[ACH];
    float scl[ACH];
#pragma unroll
    for (int c = 0; c < ACH; c++) {
        Ap[c] = A + (size_t)(row0 + lr + 32 * c) * K + kq;
        scl[c] = NORM ? invr[row0 + lr + 32 * c] : 1.0f;
    }
    const float* Wp[4];
#pragma unroll
    for (int c = 0; c < 4; c++)
        Wp[c] = W + (size_t)(col0 + lr + 32 * c) * K + kq;

    uint32_t saBase = (uint32_t)__cvta_generic_to_shared(&SA[0][0][0]);
    uint32_t swBase = (uint32_t)__cvta_generic_to_shared(&SW[0][0][0]);
    const uint32_t aAddr = saBase + (((wm * 32 + (lane & 15)) * 20) + (lane >> 4) * 4) * 4;
    const uint32_t bAddr = swBase +
        (((wn * WCOLS + (lane & 7) + ((lane >> 4) << 3)) * 20) + ((lane >> 3) & 1) * 4) * 4;
    constexpr uint32_t AHL = BM * 20 * 4;
    constexpr uint32_t WHL = 128 * 20 * 4;

    float acc[2][NT][4];
#pragma unroll
    for (int a = 0; a < 2; a++)
#pragma unroll
        for (int b = 0; b < NT; b++)
#pragma unroll
            for (int c = 0; c < 4; c++) acc[a][b][c] = 0.f;

    const int nk = K / 32;
    float4 pa[ACH], pw[4];
#pragma unroll
    for (int c = 0; c < ACH; c++) pa[c] = *(const float4*)(Ap[c]);
#pragma unroll
    for (int c = 0; c < 4; c++) pw[c] = *(const float4*)(Wp[c]);

    for (int i = 0; i < nk; i++) {
#pragma unroll
        for (int c = 0; c < ACH; c++) {
            int m = lr + 32 * c;
            float x0 = pa[c].x, x1 = pa[c].y, x2 = pa[c].z, x3 = pa[c].w;
            if (NORM) { x0 *= scl[c]; x1 *= scl[c]; x2 *= scl[c]; x3 *= scl[c]; }
            uint32_t h0, l0h, h1, l1h;
            split2(x0, x1, h0, l0h);
            split2(x2, x3, h1, l1h);
            SA[0][m][(kq >> 1)] = h0;
            SA[0][m][(kq >> 1) + 1] = h1;
            SA[1][m][(kq >> 1)] = l0h;
            SA[1][m][(kq >> 1) + 1] = l1h;
        }
#pragma unroll
        for (int c = 0; c < 4; c++) {
            int n = lr + 32 * c;
            uint32_t h0, l0h, h1, l1h;
            split2(pw[c].x, pw[c].y, h0, l0h);
            split2(pw[c].z, pw[c].w, h1, l1h);
            SW[0][n][(kq >> 1)] = h0;
            SW[0][n][(kq >> 1) + 1] = h1;
            SW[1][n][(kq >> 1)] = l0h;
            SW[1][n][(kq >> 1) + 1] = l1h;
        }
        __syncthreads();
        if (i + 1 < nk) {
            int ko = (i + 1) * 32;
#pragma unroll
            for (int c = 0; c < ACH; c++) pa[c] = *(const float4*)(Ap[c] + ko);
#pragma unroll
            for (int c = 0; c < 4; c++) pw[c] = *(const float4*)(Wp[c] + ko);
        }
#pragma unroll
        for (int kk = 0; kk < 2; kk++) {
            uint32_t ah[2][4], al[2][4];
#pragma unroll
            for (int mt = 0; mt < 2; mt++) {
                uint32_t base = aAddr + mt * 1280 + kk * 32;
                LDSM4(ah[mt], base);
                LDSM4(al[mt], base + AHL);
            }
#pragma unroll
            for (int p = 0; p < NP; p++) {
                uint32_t bh[4], bl[4];
                uint32_t base = bAddr + p * 1280 + kk * 32;
                LDSM4(bh, base);
                LDSM4(bl, base + WHL);
#pragma unroll
                for (int mt = 0; mt < 2; mt++) {
                    MMA_BF16(acc[mt][2 * p], ah[mt][0], ah[mt][1], ah[mt][2], ah[mt][3], bh[0], bh[1]);
                    MMA_BF16(acc[mt][2 * p], al[mt][0], al[mt][1], al[mt][2], al[mt][3], bh[0], bh[1]);
                    MMA_BF16(acc[mt][2 * p], ah[mt][0], ah[mt][1], ah[mt][2], ah[mt][3], bl[0], bl[1]);
                    MMA_BF16(acc[mt][2 * p + 1], ah[mt][0], ah[mt][1], ah[mt][2], ah[mt][3], bh[2], bh[3]);
                    MMA_BF16(acc[mt][2 * p + 1], al[mt][0], al[mt][1], al[mt][2], al[mt][3], bh[2], bh[3]);
                    MMA_BF16(acc[mt][2 * p + 1], ah[mt][0], ah[mt][1], ah[mt][2], ah[mt][3], bl[2], bl[3]);
                }
            }
        }
        __syncthreads();
    }

    if (ROPE) {
        // BM=128/256thr: WCOLS==64 -> warp slice is exactly one head.
        const int sect = col0 / DD;                  // 0=q, 1=k, 2=v
        const int hd = (col0 % DD) / 64 + wn;        // head index
#pragma unroll
        for (int mt = 0; mt < 2; mt++) {
#pragma unroll
            for (int half = 0; half < 2; half++) {
                int row = row0 + wm * 32 + mt * 16 + g + half * 8;
                int bidx = row >> 10, pos = row & (LL - 1);
                float v0[NT], v1[NT];
#pragma unroll
                for (int nt = 0; nt < NT; nt++) {
                    int col = col0 + wn * WCOLS + nt * 8 + tg * 2;
                    v0[nt] = acc[mt][nt][half * 2] + bias[col];
                    v1[nt] = acc[mt][nt][half * 2 + 1] + bias[col + 1];
                }
                size_t ob = (((size_t)bidx * HH + hd) * LL + pos) * 32;
                if (sect == 2) {
#pragma unroll
                    for (int nt = 0; nt < NT; nt++) {
                        int d = nt * 8 + tg * 2;
                        uint32_t hi, lo;
                        split2(v0[nt], v1[nt], hi, lo);
                        ovh[ob + (d >> 1)] = hi;
                        ovl[ob + (d >> 1)] = lo;
                    }
                } else {
                    uint32_t* th = (sect == 0) ? oqh : okh;
                    uint32_t* tl = (sect == 0) ? oql : okl;
#pragma unroll
                    for (int nt = 0; nt < NT / 2; nt++) {
                        int d = nt * 8 + tg * 2;     // 0..31
                        float c0 = g_cos[pos * 32 + d], sn0 = g_sin[pos * 32 + d];
                        float c1 = g_cos[pos * 32 + d + 1], sn1 = g_sin[pos * 32 + d + 1];
                        float rl0 = v0[nt] * c0 - v0[nt + NT / 2] * sn0;
                        float rl1 = v1[nt] * c1 - v1[nt + NT / 2] * sn1;
                        float rh0 = v0[nt + NT / 2] * c0 + v0[nt] * sn0;
                        float rh1 = v1[nt + NT / 2] * c1 + v1[nt] * sn1;
                        uint32_t hi, lo;
                        split2(rl0, rl1, hi, lo);
                        th[ob + (d >> 1)] = hi;
                        tl[ob + (d >> 1)] = lo;
                        split2(rh0, rh1, hi, lo);
                        th[ob + (d >> 1) + 16] = hi;
                        tl[ob + (d >> 1) + 16] = lo;
                    }
                }
            }
        }
        return;
    }

#pragma unroll
    for (int mt = 0; mt < 2; mt++) {
#pragma unroll
        for (int nt = 0; nt < NT; nt++) {
            int col = col0 + wn * WCOLS + nt * 8 + tg * 2;
            float b0 = bias[col], b1 = bias[col + 1];
#pragma unroll
            for (int half = 0; half < 2; half++) {
                int row = row0 + wm * 32 + mt * 16 + g + half * 8;
                float v0 = acc[mt][nt][half * 2] + b0;
                float v1 = acc[mt][nt][half * 2 + 1] + b1;
                if (ACT == 1) { v0 = gelu_f(v0); v1 = gelu_f(v1); }
                float* op = out + (size_t)row * N + col;
                if (RESID) { v0 += op[0]; v1 += op[1]; }
                op[0] = v0; op[1] = v1;
            }
        }
    }
}

// ---------------- tensor-core windowed flash attention (3xBF16, pre-split inputs) ----------------
__global__ void __launch_bounds__(256) attn_tc(
    const uint32_t* __restrict__ qh, const uint32_t* __restrict__ ql,
    const uint32_t* __restrict__ kh, const uint32_t* __restrict__ kl,
    const uint32_t* __restrict__ vh, const uint32_t* __restrict__ vl,
    const float* __restrict__ biasb, float* __restrict__ y) {
    __shared__ uint32_t SK[2 * 64 * 36];
    __shared__ uint32_t SV[2 * 64 * 36];

    const int q0 = blockIdx.x * 64;
    const int hh = blockIdx.y, b = blockIdx.z;
    const int tid = threadIdx.x, lane = tid & 31, w = tid >> 5;
    const int wg = w >> 2, mt = w & 3;
    const int g = lane >> 2, tg = lane & 3;
    const int m0 = mt * 16;

    const int jstart = max(q0 - WIN, 0);
    const int jend = min(q0 + 64 + WIN, LL);
    const int nt = (jend - jstart) >> 6;

    const size_t bho = ((size_t)b * HH + hh) * LL * 32;
    const float* bb = biasb + (size_t)b * LL * BW;

    {
        int row = tid >> 2, seg = tid & 3;
        size_t off = bho + (size_t)(q0 + row) * 32 + seg * 8;
        uint32_t* dh_ = SK + row * 36 + seg * 8;
        uint32_t* dl_ = SK + 2304 + row * 36 + seg * 8;
        *(uint4*)(dh_) = *(const uint4*)(qh + off);
        *(uint4*)(dh_ + 4) = *(const uint4*)(qh + off + 4);
        *(uint4*)(dl_) = *(const uint4*)(ql + off);
        *(uint4*)(dl_ + 4) = *(const uint4*)(ql + off + 4);
    }
    __syncthreads();
    uint32_t qfh[4][4], qfl[4][4];
    {
        uint32_t qA = (uint32_t)__cvta_generic_to_shared(SK) +
                      (((m0 + (lane & 15)) * 36 + (lane >> 4) * 4) << 2);
#pragma unroll
        for (int kk = 0; kk < 4; kk++) {
            LDSM4(qfh[kk], qA + kk * 32);
            LDSM4(qfl[kk], qA + 9216 + kk * 32);
        }
    }
    __syncthreads();

    const uint32_t kA = (uint32_t)__cvta_generic_to_shared(SK) +
        ((((lane & 7) + ((lane >> 4) << 3) + wg * 32) * 36 + ((lane >> 3) & 1) * 4) << 2);
    const uint32_t vA = (uint32_t)__cvta_generic_to_shared(SV) +
        ((((lane & 15) + wg * 32) * 36 + (lane >> 4) * 4) << 2);

    float mX0 = -3.0e38f, mX1 = -3.0e38f, lX0 = 0.f, lX1 = 0.f;
    float o[8][4];
#pragma unroll
    for (int d = 0; d < 8; d++)
#pragma unroll
        for (int c = 0; c < 4; c++) o[d][c] = 0.f;

    const int qi0 = q0 + m0 + g;
    const float* brow0 = bb + (size_t)qi0 * BW;
    const float* brow1 = bb + (size_t)(qi0 + 8) * BW;

    for (int t = 0; t < nt; t++) {
        int j0 = jstart + t * 64;
        {
            int row = tid >> 2, seg = tid & 3;
            size_t off = bho + (size_t)(j0 + row) * 32 + seg * 8;
            uint32_t* kh_ = SK + row * 36 + seg * 8;
            uint32_t* kl_ = SK + 2304 + row * 36 + seg * 8;
            uint32_t* vh_ = SV + row * 36 + seg * 8;
            uint32_t* vl_ = SV + 2304 + row * 36 + seg * 8;
            *(uint4*)(kh_) = *(const uint4*)(kh + off);
            *(uint4*)(kh_ + 4) = *(const uint4*)(kh + off + 4);
            *(uint4*)(kl_) = *(const uint4*)(kl + off);
            *(uint4*)(kl_ + 4) = *(const uint4*)(kl + off + 4);
            *(uint4*)(vh_) = *(const uint4*)(vh + off);
            *(uint4*)(vh_ + 4) = *(const uint4*)(vh + off + 4);
            *(uint4*)(vl_) = *(const uint4*)(vl + off);
            *(uint4*)(vl_ + 4) = *(const uint4*)(vl + off + 4);
        }
        __syncthreads();

        float acc[4][4];
#pragma unroll
        for (int d = 0; d < 4; d++)
#pragma unroll
            for (int c = 0; c < 4; c++) acc[d][c] = 0.f;
#pragma unroll
        for (int kk = 0; kk < 4; kk++) {
#pragma unroll
            for (int pr = 0; pr < 2; pr++) {
                uint32_t bh4[4], bl4[4];
                uint32_t a = kA + pr * 2304 + kk * 32;
                LDSM4(bh4, a);
                LDSM4(bl4, a + 9216);
                MMA_BF16(acc[2 * pr], qfh[kk][0], qfh[kk][1], qfh[kk][2], qfh[kk][3], bh4[0], bh4[1]);
                MMA_BF16(acc[2 * pr], qfl[kk][0], qfl[kk][1], qfl[kk][2], qfl[kk][3], bh4[0], bh4[1]);
                MMA_BF16(acc[2 * pr], qfh[kk][0], qfh[kk][1], qfh[kk][2], qfh[kk][3], bl4[0], bl4[1]);
                MMA_BF16(acc[2 * pr + 1], qfh[kk][0], qfh[kk][1], qfh[kk][2], qfh[kk][3], bh4[2], bh4[3]);
                MMA_BF16(acc[2 * pr + 1], qfl[kk][0], qfl[kk][1], qfl[kk][2], qfl[kk][3], bh4[2], bh4[3]);
                MMA_BF16(acc[2 * pr + 1], qfh[kk][0], qfh[kk][1], qfh[kk][2], qfh[kk][3], bl4[2], bl4[3]);
            }
        }

        bool needmask = (j0 < q0 - 65) || (j0 > q0 + 65);
        int jb = j0 + wg * 32 + 2 * tg;
#pragma unroll
        for (int d = 0; d < 4; d++) {
            int j = jb + 8 * d;
            int i0 = j - qi0 + WIN;
            float b00 = brow0[min(max(i0, 0), 256)];
            float b01 = brow0[min(max(i0 + 1, 0), 256)];
            float b10 = brow1[min(max(i0 - 8, 0), 256)];
            float b11 = brow1[min(max(i0 - 7, 0), 256)];
            float s0 = fmaf(acc[d][0], 0.125f, b00);
            float s1 = fmaf(acc[d][1], 0.125f, b01);
            float s2 = fmaf(acc[d][2], 0.125f, b10);
            float s3 = fmaf(acc[d][3], 0.125f, b11);
            if (needmask) {
                if ((unsigned)i0 > 256u) s0 = -3.0e38f;
                if ((unsigned)(i0 + 1) > 256u) s1 = -3.0e38f;
                if ((unsigned)(i0 - 8) > 256u) s2 = -3.0e38f;
                if ((unsigned)(i0 - 7) > 256u) s3 = -3.0e38f;
            }
            acc[d][0] = s0; acc[d][1] = s1; acc[d][2] = s2; acc[d][3] = s3;
        }
        float tm0 = -3.0e38f, tm1 = -3.0e38f;
#pragma unroll
        for (int d = 0; d < 4; d++) {
            tm0 = fmaxf(tm0, fmaxf(acc[d][0], acc[d][1]));
            tm1 = fmaxf(tm1, fmaxf(acc[d][2], acc[d][3]));
        }
        tm0 = fmaxf(tm0, __shfl_xor_sync(0xffffffffu, tm0, 1));
        tm0 = fmaxf(tm0, __shfl_xor_sync(0xffffffffu, tm0, 2));
        tm1 = fmaxf(tm1, __shfl_xor_sync(0xffffffffu, tm1, 1));
        tm1 = fmaxf(tm1, __shfl_xor_sync(0xffffffffu, tm1, 2));
        float mn0 = fmaxf(mX0, tm0), mn1 = fmaxf(mX1, tm1);
        float f0 = __expf(mX0 - mn0), f1 = __expf(mX1 - mn1);
        mX0 = mn0; mX1 = mn1;
        lX0 *= f0; lX1 *= f1;
#pragma unroll
        for (int d = 0; d < 8; d++) {
            o[d][0] *= f0; o[d][1] *= f0; o[d][2] *= f1; o[d][3] *= f1;
        }
#pragma unroll
        for (int d = 0; d < 4; d++) {
            float p0 = __expf(acc[d][0] - mn0);
            float p1 = __expf(acc[d][1] - mn0);
            float p2 = __expf(acc[d][2] - mn1);
            float p3 = __expf(acc[d][3] - mn1);
            lX0 += p0 + p1; lX1 += p2 + p3;
            acc[d][0] = p0; acc[d][1] = p1; acc[d][2] = p2; acc[d][3] = p3;
        }
#pragma unroll
        for (int c = 0; c < 2; c++) {
            int d0 = 2 * c, d1 = 2 * c + 1;
            uint32_t ph0, pl0, ph1, pl1, ph2, pl2, ph3, pl3;
            split2(acc[d0][0], acc[d0][1], ph0, pl0);
            split2(acc[d0][2], acc[d0][3], ph1, pl1);
            split2(acc[d1][0], acc[d1][1], ph2, pl2);
            split2(acc[d1][2], acc[d1][3], ph3, pl3);
#pragma unroll
            for (int pr = 0; pr < 4; pr++) {
                uint32_t vh4[4], vl4[4];
                uint32_t a = vA + c * 2304 + pr * 32;
                LDSM4T(vh4, a);
                LDSM4T(vl4, a + 9216);
                MMA_BF16(o[2 * pr], ph0, ph1, ph2, ph3, vh4[0], vh4[1]);
                MMA_BF16(o[2 * pr], pl0, pl1, pl2, pl3, vh4[0], vh4[1]);
                MMA_BF16(o[2 * pr], ph0, ph1, ph2, ph3, vl4[0], vl4[1]);
                MMA_BF16(o[2 * pr + 1], ph0, ph1, ph2, ph3, vh4[2], vh4[3]);
                MMA_BF16(o[2 * pr + 1], pl0, pl1, pl2, pl3, vh4[2], vh4[3]);
                MMA_BF16(o[2 * pr + 1], ph0, ph1, ph2, ph3, vl4[2], vl4[3]);
            }
        }
        __syncthreads();
    }

    lX0 += __shfl_xor_sync(0xffffffffu, lX0, 1);
    lX0 += __shfl_xor_sync(0xffffffffu, lX0, 2);
    lX1 += __shfl_xor_sync(0xffffffffu, lX1, 1);
    lX1 += __shfl_xor_sync(0xffffffffu, lX1, 2);

    float* mo = (float*)SK;
    float* ml = (float*)SV;
    if (wg == 1) {
#pragma unroll
        for (int d = 0; d < 8; d++) {
            *(float2*)&mo[(m0 + g) * 66 + 8 * d + 2 * tg] = make_float2(o[d][0], o[d][1]);
            *(float2*)&mo[(m0 + 8 + g) * 66 + 8 * d + 2 * tg] = make_float2(o[d][2], o[d][3]);
        }
        if (tg == 0) {
            ml[(m0 + g) * 2] = mX0; ml[(m0 + g) * 2 + 1] = lX0;
            ml[(m0 + 8 + g) * 2] = mX1; ml[(m0 + 8 + g) * 2 + 1] = lX1;
        }
    }
    __syncthreads();
    if (wg == 0) {
        int r0 = m0 + g, r1 = m0 + 8 + g;
        float om0 = ml[r0 * 2], ol0 = ml[r0 * 2 + 1];
        float om1 = ml[r1 * 2], ol1 = ml[r1 * 2 + 1];
        float mnA = fmaxf(mX0, om0);
        float fa = __expf(mX0 - mnA), fb = __expf(om0 - mnA);
        float invA = 1.0f / (lX0 * fa + ol0 * fb);
        float mnB = fmaxf(mX1, om1);
        float fc = __expf(mX1 - mnB), fd = __expf(om1 - mnB);
        float invB = 1.0f / (lX1 * fc + ol1 * fd);
        float* y0 = y + ((size_t)(b * LL + q0 + r0)) * DD + hh * DHH;
        float* y1 = y + ((size_t)(b * LL + q0 + r1)) * DD + hh * DHH;
#pragma unroll
        for (int d = 0; d < 8; d++) {
            float2 e0 = *(float2*)&mo[r0 * 66 + 8 * d + 2 * tg];
            float2 e1 = *(float2*)&mo[r1 * 66 + 8 * d + 2 * tg];
            float2 w0, w1;
            w0.x = (o[d][0] * fa + e0.x * fb) * invA;
            w0.y = (o[d][1] * fa + e0.y * fb) * invA;
            w1.x = (o[d][2] * fc + e1.x * fd) * invB;
            w1.y = (o[d][3] * fc + e1.y * fd) * invB;
            *(float2*)&y0[8 * d + 2 * tg] = w0;
            *(float2*)&y1[8 * d + 2 * tg] = w1;
        }
    }
}

// ---------------- driver ----------------
extern "C" void kernel_launch(void* const* d_in, const int* in_sizes, int n_in,
                              void* d_out, int out_size) {
    const float* s_in  = (const float*)d_in[0];
    const float* pair  = (const float*)d_in[1];
    const float* qkv_w = (const float*)d_in[2];
    const float* qkv_b = (const float*)d_in[3];
    const float* out_w = (const float*)d_in[4];
    const float* out_b = (const float*)d_in[5];
    const float* fc1_w = (const float*)d_in[6];
    const float* fc1_b = (const float*)d_in[7];
    const float* fc2_w = (const float*)d_in[8];
    const float* fc2_b = (const float*)d_in[9];
    const float* ln_g  = (const float*)d_in[10];
    const float* ln_b  = (const float*)d_in[11];
    const float* pb_w  = (const float*)d_in[12];
    const float* pb_b  = (const float*)d_in[13];
    float* s = (float*)d_out;

    float *p_y, *p_u, *p_bias, *p_inv;
    uint32_t *p_qh, *p_ql, *p_kh, *p_kl, *p_vh, *p_vl;
    cudaGetSymbolAddress((void**)&p_y, g_y);
    cudaGetSymbolAddress((void**)&p_u, g_u);
    cudaGetSymbolAddress((void**)&p_bias, g_bias);
    cudaGetSymbolAddress((void**)&p_inv, g_inv);
    cudaGetSymbolAddress((void**)&p_qh, g_qh);
    cudaGetSymbolAddress((void**)&p_ql, g_ql);
    cudaGetSymbolAddress((void**)&p_kh, g_kh);
    cudaGetSymbolAddress((void**)&p_kl, g_kl);
    cudaGetSymbolAddress((void**)&p_vh, g_vh);
    cudaGetSymbolAddress((void**)&p_vl, g_vl);

    cudaMemcpyAsync(s, s_in, sizeof(float) * BB * LL * DD, cudaMemcpyDeviceToDevice, 0);

    rope_table_kernel<<<(LL * 32 + 255) / 256, 256>>>();

    {
        int nwarps = BB * LL * 257;
        int blocks = (nwarps * 32 + 255) / 256;
        bias_kernel<<<blocks, 256>>>(pair, ln_g, ln_b, pb_w, pb_b, p_bias);
    }

    const int NROWS = BB * LL;
    for (int l = 0; l < NLAYER; l++) {
        invrms_kernel<<<NROWS / 8, 256>>>(s, p_inv);
        gemm_tc<128, 0, 0, 1, 1><<<dim3(3 * DD / 128, NROWS / 128), 256>>>(
            s, qkv_w + (size_t)l * 3 * DD * DD, qkv_b + (size_t)l * 3 * DD, nullptr, p_inv,
            p_qh, p_ql, p_kh, p_kl, p_vh, p_vl, DD, 3 * DD);
        attn_tc<<<dim3(LL / 64, HH, BB), 256>>>(
            p_qh, p_ql, p_kh, p_kl, p_vh, p_vl, p_bias + (size_t)l * BB * LL * BW, p_y);
        gemm_tc<64, 0, 1, 0, 0><<<dim3(DD / 128, NROWS / 64), 256>>>(
            p_y, out_w + (size_t)l * DD * DD, out_b + (size_t)l * DD, s, nullptr,
            nullptr, nullptr, nullptr, nullptr, nullptr, nullptr, DD, DD);
        invrms_kernel<<<NROWS / 8, 256>>>(s, p_inv);
        gemm_tc<128, 1, 0, 1, 0><<<dim3(MLPD / 128, NROWS / 128), 256>>>(
            s, fc1_w + (size_t)l * MLPD * DD, fc1_b + (size_t)l * MLPD, p_u, p_inv,
            nullptr, nullptr, nullptr, nullptr, nullptr, nullptr, DD, MLPD);
        gemm_tc<64, 0, 1, 0, 0><<<dim3(DD / 128, NROWS / 64), 256>>>(
            p_u, fc2_w + (size_t)l * DD * MLPD, fc2_b + (size_t)l * DD, s, nullptr,
            nullptr, nullptr, nullptr, nullptr, nullptr, nullptr, MLPD, DD);
    }
}